// round 6
// baseline (speedup 1.0000x reference)
#include <cuda_runtime.h>
#include <cstdint>
#include <cstddef>
#include <algorithm>

// ---------------- problem constants ----------------
#define BB   256        // batch
#define FD   128        // feature dim (also E)
#define DEG  64         // max degree
#define S1N  (BB * 50)  // 12800 rows per chain at hop-1
#define M1   (2 * S1N)  // 25600 rows (both chains) for the big GEMM

typedef unsigned long long ull;

// ---------------- device scratch (static, no runtime alloc) ----------------
__device__ int   g_s1[2][S1N];
__device__ float g_agg1[(size_t)M1 * 384];      // hop1 agg (39.3 MB)
__device__ float g_h1  [(size_t)M1 * 128];      // hop1 hidden
__device__ float g_h0  [(size_t)2 * BB * 128];  // hop0 hidden

struct ColsParam {
    int out25[2][25];
    int in25 [2][25];
    int out10[2][10];
    int in10 [2][10];
};

// ---------------- host-side JAX threefry reproduction (validated R5) ----------------
namespace {

struct KeyPair { uint32_t a, b; };

static inline uint32_t rotl32(uint32_t x, int d) { return (x << d) | (x >> (32 - d)); }

static void tf2x32(uint32_t k0, uint32_t k1, uint32_t x0, uint32_t x1,
                   uint32_t& o0, uint32_t& o1) {
    const uint32_t ks2 = k0 ^ k1 ^ 0x1BD11BDAu;
    const int ra[4] = {13, 15, 26, 6};
    const int rb[4] = {17, 29, 16, 24};
    x0 += k0; x1 += k1;
    for (int i = 0; i < 4; i++) { x0 += x1; x1 = rotl32(x1, ra[i]); x1 ^= x0; }
    x0 += k1; x1 += ks2 + 1u;
    for (int i = 0; i < 4; i++) { x0 += x1; x1 = rotl32(x1, rb[i]); x1 ^= x0; }
    x0 += ks2; x1 += k0 + 2u;
    for (int i = 0; i < 4; i++) { x0 += x1; x1 = rotl32(x1, ra[i]); x1 ^= x0; }
    x0 += k0; x1 += k1 + 3u;
    for (int i = 0; i < 4; i++) { x0 += x1; x1 = rotl32(x1, rb[i]); x1 ^= x0; }
    x0 += k1; x1 += ks2 + 4u;
    for (int i = 0; i < 4; i++) { x0 += x1; x1 = rotl32(x1, ra[i]); x1 ^= x0; }
    x0 += ks2; x1 += k0 + 5u;
    o0 = x0; o1 = x1;
}

// modern JAX (threefry_partitionable): child i = cipher(key, (0, i))
static KeyPair split_child(KeyPair k, uint32_t i, uint32_t /*num*/) {
    KeyPair r; tf2x32(k.a, k.b, 0u, i, r.a, r.b); return r;
}
static void bits64(KeyPair k, uint32_t* out /*64*/) {
    for (uint32_t i = 0; i < 64; i++) {
        uint32_t a, b; tf2x32(k.a, k.b, 0u, i, a, b);
        out[i] = a ^ b;
    }
}

static void perm64(KeyPair key, int* out /*64*/) {
    KeyPair sub = split_child(key, 1, 2);
    uint32_t sk[64]; int idx[64];
    bits64(sub, sk);
    for (int i = 0; i < 64; i++) idx[i] = i;
    std::stable_sort(idx, idx + 64, [&](int x, int y) { return sk[x] < sk[y]; });
    for (int i = 0; i < 64; i++) out[i] = idx[i];
}

static void compute_cols(ColsParam& cp) {
    KeyPair base{0u, 42u};
    KeyPair kc[2] = { split_child(base, 0, 2), split_child(base, 1, 2) };
    int p[64];
    for (int c = 0; c < 2; c++) {
        KeyPair K = kc[c];
        KeyPair Kn = split_child(K, 0, 3);
        KeyPair ka = split_child(K, 1, 3);
        KeyPair kb = split_child(K, 2, 3);
        perm64(ka, p); for (int j = 0; j < 25; j++) cp.out25[c][j] = p[j];
        perm64(kb, p); for (int j = 0; j < 25; j++) cp.in25 [c][j] = p[j];
        K = Kn;
        ka = split_child(K, 1, 3);
        kb = split_child(K, 2, 3);
        perm64(ka, p); for (int j = 0; j < 10; j++) cp.out10[c][j] = p[j];
        perm64(kb, p); for (int j = 0; j < 10; j++) cp.in10 [c][j] = p[j];
    }
}

} // namespace

// ---------------- device helpers ----------------
__device__ __forceinline__ ull ffma2(ull a, ull b, ull c) {
    ull d;
    asm("fma.rn.f32x2 %0, %1, %2, %3;" : "=l"(d) : "l"(a), "l"(b), "l"(c));
    return d;
}
__device__ __forceinline__ ull pack2(float x, float y) {
    ull r;
    asm("mov.b64 %0, {%1, %2};" : "=l"(r) : "f"(x), "f"(y));
    return r;
}
__device__ __forceinline__ float sigf(float x) { return 1.0f / (1.0f + __expf(-x)); }

__device__ __forceinline__ void add4(float4& a, const float4 b) {
    a.x += b.x; a.y += b.y; a.z += b.z; a.w += b.w;
}
__device__ __forceinline__ float4 scale4(const float4 a, float s) {
    return make_float4(a.x * s, a.y * s, a.z * s, a.w * s);
}

// ---------------- kernels ----------------

// s1[c][b*50 + t] : t<25 -> out-neighbor cols, t>=25 -> in-neighbor cols
__global__ void k_sample(const int* __restrict__ nodes1, const int* __restrict__ nodes2,
                         const int* __restrict__ nout, const int* __restrict__ nin,
                         ColsParam cp) {
    int c = blockIdx.y, b = blockIdx.x, t = threadIdx.x; // t in [0,50)
    int v = (c ? nodes2 : nodes1)[b];
    int idx = (t < 25) ? nout[v * DEG + cp.out25[c][t]]
                       : nin [v * DEG + cp.in25 [c][t - 25]];
    g_s1[c][b * 50 + t] = idx;
}

// hop-1 aggregation: warp per row, float4 lanes, shfl-broadcast indices.
__global__ __launch_bounds__(256) void k_agg_hop1(const int* __restrict__ nout,
                                                  const int* __restrict__ nin,
                                                  const float* __restrict__ feat,
                                                  ColsParam cp) {
    int c = blockIdx.y;
    int w = threadIdx.x >> 5, lane = threadIdx.x & 31;
    int i = blockIdx.x * 8 + w;   // 0..S1N-1
    int s = g_s1[c][i];
    int nb = 0;
    if (lane < 10)      nb = nout[s * DEG + cp.out10[c][lane]];
    else if (lane < 20) nb = nin [s * DEG + cp.in10 [c][lane - 10]];

    const float4* F = (const float4*)feat;      // row stride 32 float4
    float4 self = F[(size_t)s * 32 + lane];
    float4 so = make_float4(0.f, 0.f, 0.f, 0.f);
    float4 si = make_float4(0.f, 0.f, 0.f, 0.f);
#pragma unroll
    for (int j = 0; j < 10; j++) {
        int n = __shfl_sync(0xffffffffu, nb, j);
        add4(so, F[(size_t)n * 32 + lane]);
    }
#pragma unroll
    for (int j = 10; j < 20; j++) {
        int n = __shfl_sync(0xffffffffu, nb, j);
        add4(si, F[(size_t)n * 32 + lane]);
    }
    float4* o = (float4*)(g_agg1 + ((size_t)c * S1N + i) * 384);
    o[lane]      = self;
    o[32 + lane] = scale4(so, 1.0f / 10.0f);
    o[64 + lane] = scale4(si, 1.0f / 10.0f);
}

// big GEMM: C[M1,128] = sigmoid(agg1[M1,384] @ W[384,128]) using packed fp32 FFMA2.
// Tile 64x128, BK=16, 256 threads; per thread 4 rows x 8 cols = 16 f32x2 accs.
__global__ __launch_bounds__(256) void k_gemm_h1(const float* __restrict__ W) {
    __shared__ __align__(16) ull sA2[16][66];  // [kk][row] = {a,a}; 66 => 528B row, 16B-aligned
    __shared__ __align__(16) ull sB2[16][66];  // [kk][colpair]
    const float* A = g_agg1;
    const int bm  = blockIdx.x * 64;
    const int tid = threadIdx.x;
    const int tx  = tid & 15;     // col pairs tx*4..tx*4+3 (cols tx*8..tx*8+7)
    const int ty  = tid >> 4;     // rows ty*4..ty*4+3
    const int r   = tid >> 2, q  = tid & 3;   // A stage map
    const int kr  = tid >> 4, c16 = tid & 15; // B stage map

    ull acc[4][4];
#pragma unroll
    for (int i = 0; i < 4; i++)
#pragma unroll
        for (int j = 0; j < 4; j++) acc[i][j] = 0ull;

    for (int k0 = 0; k0 < 384; k0 += 16) {
        float4 av = *(const float4*)&A[(size_t)(bm + r) * 384 + k0 + q * 4];
        sA2[q * 4 + 0][r] = pack2(av.x, av.x);
        sA2[q * 4 + 1][r] = pack2(av.y, av.y);
        sA2[q * 4 + 2][r] = pack2(av.z, av.z);
        sA2[q * 4 + 3][r] = pack2(av.w, av.w);
        union { float4 f; ull u[2]; } w0, w1;
        w0.f = *(const float4*)&W[(size_t)(k0 + kr) * 128 + c16 * 8];
        w1.f = *(const float4*)&W[(size_t)(k0 + kr) * 128 + c16 * 8 + 4];
        sB2[kr][c16 * 4 + 0] = w0.u[0];
        sB2[kr][c16 * 4 + 1] = w0.u[1];
        sB2[kr][c16 * 4 + 2] = w1.u[0];
        sB2[kr][c16 * 4 + 3] = w1.u[1];
        __syncthreads();
#pragma unroll
        for (int kk = 0; kk < 16; kk++) {
            ulonglong2 a01 = *(const ulonglong2*)&sA2[kk][ty * 4];
            ulonglong2 a23 = *(const ulonglong2*)&sA2[kk][ty * 4 + 2];
            ulonglong2 b01 = *(const ulonglong2*)&sB2[kk][tx * 4];
            ulonglong2 b23 = *(const ulonglong2*)&sB2[kk][tx * 4 + 2];
            ull a[4] = { a01.x, a01.y, a23.x, a23.y };
            ull b[4] = { b01.x, b01.y, b23.x, b23.y };
#pragma unroll
            for (int i = 0; i < 4; i++)
#pragma unroll
                for (int j = 0; j < 4; j++)
                    acc[i][j] = ffma2(a[i], b[j], acc[i][j]);
        }
        __syncthreads();
    }
#pragma unroll
    for (int i = 0; i < 4; i++) {
        int row = bm + ty * 4 + i;
        float o[8];
#pragma unroll
        for (int j = 0; j < 4; j++) {
            union { ull u; float2 f; } uu; uu.u = acc[i][j];
            o[2 * j]     = sigf(uu.f.x);
            o[2 * j + 1] = sigf(uu.f.y);
        }
        *(float4*)&g_h1[(size_t)row * 128 + tx * 8]     = make_float4(o[0], o[1], o[2], o[3]);
        *(float4*)&g_h1[(size_t)row * 128 + tx * 8 + 4] = make_float4(o[4], o[5], o[6], o[7]);
    }
}

// fused hop-0: gather/mean agg0 (16 rows) in smem, then GEMM @W_in -> g_h0
__global__ __launch_bounds__(256) void k_h0(const int* __restrict__ nodes1,
                                            const int* __restrict__ nodes2,
                                            const float* __restrict__ feat,
                                            const float* __restrict__ W) {
    __shared__ float sAgg[16][388];
    __shared__ float sW[16][132];
    __shared__ int   sIdx[16][50];
    __shared__ int   sSelf[16];
    int c = blockIdx.y, b0 = blockIdx.x * 16;
    int tid = threadIdx.x;
    if (tid < 16) sSelf[tid] = (c ? nodes2 : nodes1)[b0 + tid];
    for (int l = tid; l < 16 * 50; l += 256)
        sIdx[l / 50][l % 50] = g_s1[c][(b0 + l / 50) * 50 + l % 50];
    __syncthreads();

    int rr = tid >> 4, l16 = tid & 15, f0 = l16 * 8;
    {
        int sv = sSelf[rr];
        float4 se0 = *(const float4*)&feat[(size_t)sv * 128 + f0];
        float4 se1 = *(const float4*)&feat[(size_t)sv * 128 + f0 + 4];
        float4 ao0 = make_float4(0, 0, 0, 0), ao1 = ao0, ai0 = ao0, ai1 = ao0;
#pragma unroll 5
        for (int j = 0; j < 25; j++) {
            int n = sIdx[rr][j];
            add4(ao0, *(const float4*)&feat[(size_t)n * 128 + f0]);
            add4(ao1, *(const float4*)&feat[(size_t)n * 128 + f0 + 4]);
        }
#pragma unroll 5
        for (int j = 25; j < 50; j++) {
            int n = sIdx[rr][j];
            add4(ai0, *(const float4*)&feat[(size_t)n * 128 + f0]);
            add4(ai1, *(const float4*)&feat[(size_t)n * 128 + f0 + 4]);
        }
        *(float4*)&sAgg[rr][f0]           = se0;
        *(float4*)&sAgg[rr][f0 + 4]       = se1;
        *(float4*)&sAgg[rr][128 + f0]     = scale4(ao0, 1.0f / 25.0f);
        *(float4*)&sAgg[rr][128 + f0 + 4] = scale4(ao1, 1.0f / 25.0f);
        *(float4*)&sAgg[rr][256 + f0]     = scale4(ai0, 1.0f / 25.0f);
        *(float4*)&sAgg[rr][256 + f0 + 4] = scale4(ai1, 1.0f / 25.0f);
    }
    __syncthreads();

    float acc[8] = {0, 0, 0, 0, 0, 0, 0, 0};
    for (int k0 = 0; k0 < 384; k0 += 16) {
        int wkr = tid >> 4, wc = (tid & 15) * 8;
        *(float4*)&sW[wkr][wc]     = *(const float4*)&W[(size_t)(k0 + wkr) * 128 + wc];
        *(float4*)&sW[wkr][wc + 4] = *(const float4*)&W[(size_t)(k0 + wkr) * 128 + wc + 4];
        __syncthreads();
#pragma unroll
        for (int kk = 0; kk < 16; kk++) {
            float a = sAgg[rr][k0 + kk];
#pragma unroll
            for (int jj = 0; jj < 8; jj++) acc[jj] += a * sW[kk][f0 + jj];
        }
        __syncthreads();
    }
#pragma unroll
    for (int jj = 0; jj < 8; jj++)
        g_h0[(size_t)(c * BB + b0 + rr) * 128 + f0 + jj] = sigf(acc[jj]);
}

// fused tail: aggL1 -> 3 head GEMMs (sigmoid) -> 3 final projections -> out
__global__ __launch_bounds__(256) void k_tail(const float* __restrict__ Wm,
                                              const float* __restrict__ Ws,
                                              const float* __restrict__ Wp,
                                              const float* __restrict__ Wdm,
                                              const float* __restrict__ Wds,
                                              const float* __restrict__ Wdp,
                                              float* __restrict__ out) {
    __shared__ float sAgg[16][388];
    __shared__ float sW[16][132];   // reused as [32][64] Wd chunks in phase C
    __shared__ float sH[16][132];
    int c = blockIdx.y, b0 = blockIdx.x * 16;
    int tid = threadIdx.x;
    int rr = tid >> 4, l16 = tid & 15, f0 = l16 * 8;

    // phase A: aggL1 rows
    {
        const float* h0 = &g_h0[(size_t)(c * BB + b0 + rr) * 128];
        float4 se0 = *(const float4*)&h0[f0];
        float4 se1 = *(const float4*)&h0[f0 + 4];
        const float* h1b = g_h1 + (size_t)(c * S1N + (b0 + rr) * 50) * 128;
        float4 ao0 = make_float4(0, 0, 0, 0), ao1 = ao0, ai0 = ao0, ai1 = ao0;
#pragma unroll 5
        for (int j = 0; j < 25; j++) {
            add4(ao0, *(const float4*)&h1b[(size_t)j * 128 + f0]);
            add4(ao1, *(const float4*)&h1b[(size_t)j * 128 + f0 + 4]);
        }
#pragma unroll 5
        for (int j = 25; j < 50; j++) {
            add4(ai0, *(const float4*)&h1b[(size_t)j * 128 + f0]);
            add4(ai1, *(const float4*)&h1b[(size_t)j * 128 + f0 + 4]);
        }
        *(float4*)&sAgg[rr][f0]           = se0;
        *(float4*)&sAgg[rr][f0 + 4]       = se1;
        *(float4*)&sAgg[rr][128 + f0]     = scale4(ao0, 1.0f / 25.0f);
        *(float4*)&sAgg[rr][128 + f0 + 4] = scale4(ao1, 1.0f / 25.0f);
        *(float4*)&sAgg[rr][256 + f0]     = scale4(ai0, 1.0f / 25.0f);
        *(float4*)&sAgg[rr][256 + f0 + 4] = scale4(ai1, 1.0f / 25.0f);
    }
    __syncthreads();

    for (int head = 0; head < 3; head++) {
        const float* W  = (head == 0) ? Wm  : (head == 1) ? Ws  : Wp;
        const float* Wd = (head == 0) ? Wdm : (head == 1) ? Wds : Wdp;

        // phase B: 16x384 @ 384x128 + sigmoid -> sH
        float acc[8] = {0, 0, 0, 0, 0, 0, 0, 0};
        for (int k0 = 0; k0 < 384; k0 += 16) {
            int wkr = tid >> 4, wc = (tid & 15) * 8;
            *(float4*)&sW[wkr][wc]     = *(const float4*)&W[(size_t)(k0 + wkr) * 128 + wc];
            *(float4*)&sW[wkr][wc + 4] = *(const float4*)&W[(size_t)(k0 + wkr) * 128 + wc + 4];
            __syncthreads();
#pragma unroll
            for (int kk = 0; kk < 16; kk++) {
                float a = sAgg[rr][k0 + kk];
#pragma unroll
                for (int jj = 0; jj < 8; jj++) acc[jj] += a * sW[kk][f0 + jj];
            }
            __syncthreads();
        }
#pragma unroll
        for (int jj = 0; jj < 8; jj++) sH[rr][f0 + jj] = sigf(acc[jj]);
        __syncthreads();

        // phase C: 16x128 @ 128x64 -> out
        float* sWd = &sW[0][0];    // reuse as flat [32][64]
        int d0 = (tid & 15) * 4;
        float acd[4] = {0, 0, 0, 0};
        for (int k0 = 0; k0 < 128; k0 += 32) {
            int wk = tid >> 3, wd = (tid & 7) * 8;
            *(float4*)&sWd[wk * 64 + wd]     = *(const float4*)&Wd[(size_t)(k0 + wk) * 64 + wd];
            *(float4*)&sWd[wk * 64 + wd + 4] = *(const float4*)&Wd[(size_t)(k0 + wk) * 64 + wd + 4];
            __syncthreads();
#pragma unroll
            for (int kk = 0; kk < 32; kk++) {
                float a = sH[rr][k0 + kk];
#pragma unroll
                for (int dd = 0; dd < 4; dd++) acd[dd] += a * sWd[kk * 64 + d0 + dd];
            }
            __syncthreads();
        }
        int slot = c * 3 + head;
        *(float4*)&out[((size_t)slot * BB + b0 + rr) * 64 + d0] =
            make_float4(acd[0], acd[1], acd[2], acd[3]);
        __syncthreads();
    }
}

// ---------------- launcher ----------------
extern "C" void kernel_launch(void* const* d_in, const int* in_sizes, int n_in,
                              void* d_out, int out_size) {
    (void)in_sizes; (void)n_in; (void)out_size;
    const int*   nodes1 = (const int*)  d_in[0];
    const int*   nodes2 = (const int*)  d_in[1];
    const int*   nout   = (const int*)  d_in[2];
    const int*   nin    = (const int*)  d_in[3];
    const float* feat   = (const float*)d_in[4];
    const float* W_in   = (const float*)d_in[5];
    const float* W_mean = (const float*)d_in[6];
    const float* W_std  = (const float*)d_in[7];
    const float* W_pi   = (const float*)d_in[8];
    const float* Wd_mean = (const float*)d_in[11];
    const float* Wd_std  = (const float*)d_in[12];
    const float* Wd_pi   = (const float*)d_in[13];
    float* out = (float*)d_out;

    ColsParam cp;
    compute_cols(cp);

    k_sample  <<<dim3(BB, 2), 50>>>(nodes1, nodes2, nout, nin, cp);
    k_h0      <<<dim3(16, 2), 256>>>(nodes1, nodes2, feat, W_in);
    k_agg_hop1<<<dim3(S1N / 8, 2), 256>>>(nout, nin, feat, cp);
    k_gemm_h1 <<<M1 / 64, 256>>>(W_in);
    k_tail    <<<dim3(16, 2), 256>>>(W_mean, W_std, W_pi, Wd_mean, Wd_std, Wd_pi, out);
}

// round 10
// speedup vs baseline: 1.5923x; 1.5923x over previous
#include <cuda_runtime.h>
#include <cstdint>
#include <cstddef>
#include <algorithm>

// ---------------- problem constants ----------------
#define BB   256        // batch
#define FD   128        // feature dim (also E)
#define DEG  64         // max degree
#define S1N  (BB * 50)  // 12800 rows per chain at hop-1
#define M1   (2 * S1N)  // 25600 rows (both chains) for the big GEMM

typedef unsigned long long ull;

// ---------------- device scratch (static, no runtime alloc) ----------------
__device__ int   g_s1[2][S1N];
__device__ float g_agg1[(size_t)M1 * 384];      // hop1 agg (39.3 MB)
__device__ float g_h1  [(size_t)M1 * 128];      // hop1 hidden
__device__ float g_agg0[(size_t)2 * BB * 384];  // hop0 agg
__device__ float g_h0  [(size_t)2 * BB * 128];  // hop0 hidden
__device__ float g_aggL1[(size_t)2 * BB * 384]; // layer-1 agg
__device__ float g_head[3][(size_t)2 * BB * 128]; // mean/std/pi hidden

struct ColsParam {
    int out25[2][25];
    int in25 [2][25];
    int out10[2][10];
    int in10 [2][10];
};

// ---------------- host-side JAX threefry reproduction (validated R5) ----------------
namespace {

struct KeyPair { uint32_t a, b; };

static inline uint32_t rotl32(uint32_t x, int d) { return (x << d) | (x >> (32 - d)); }

static void tf2x32(uint32_t k0, uint32_t k1, uint32_t x0, uint32_t x1,
                   uint32_t& o0, uint32_t& o1) {
    const uint32_t ks2 = k0 ^ k1 ^ 0x1BD11BDAu;
    const int ra[4] = {13, 15, 26, 6};
    const int rb[4] = {17, 29, 16, 24};
    x0 += k0; x1 += k1;
    for (int i = 0; i < 4; i++) { x0 += x1; x1 = rotl32(x1, ra[i]); x1 ^= x0; }
    x0 += k1; x1 += ks2 + 1u;
    for (int i = 0; i < 4; i++) { x0 += x1; x1 = rotl32(x1, rb[i]); x1 ^= x0; }
    x0 += ks2; x1 += k0 + 2u;
    for (int i = 0; i < 4; i++) { x0 += x1; x1 = rotl32(x1, ra[i]); x1 ^= x0; }
    x0 += k0; x1 += k1 + 3u;
    for (int i = 0; i < 4; i++) { x0 += x1; x1 = rotl32(x1, rb[i]); x1 ^= x0; }
    x0 += k1; x1 += ks2 + 4u;
    for (int i = 0; i < 4; i++) { x0 += x1; x1 = rotl32(x1, ra[i]); x1 ^= x0; }
    x0 += ks2; x1 += k0 + 5u;
    o0 = x0; o1 = x1;
}

static KeyPair split_child(KeyPair k, uint32_t i, uint32_t /*num*/) {
    KeyPair r; tf2x32(k.a, k.b, 0u, i, r.a, r.b); return r;
}
static void bits64(KeyPair k, uint32_t* out /*64*/) {
    for (uint32_t i = 0; i < 64; i++) {
        uint32_t a, b; tf2x32(k.a, k.b, 0u, i, a, b);
        out[i] = a ^ b;
    }
}

static void perm64(KeyPair key, int* out /*64*/) {
    KeyPair sub = split_child(key, 1, 2);
    uint32_t sk[64]; int idx[64];
    bits64(sub, sk);
    for (int i = 0; i < 64; i++) idx[i] = i;
    std::stable_sort(idx, idx + 64, [&](int x, int y) { return sk[x] < sk[y]; });
    for (int i = 0; i < 64; i++) out[i] = idx[i];
}

static void compute_cols(ColsParam& cp) {
    KeyPair base{0u, 42u};
    KeyPair kc[2] = { split_child(base, 0, 2), split_child(base, 1, 2) };
    int p[64];
    for (int c = 0; c < 2; c++) {
        KeyPair K = kc[c];
        KeyPair Kn = split_child(K, 0, 3);
        KeyPair ka = split_child(K, 1, 3);
        KeyPair kb = split_child(K, 2, 3);
        perm64(ka, p); for (int j = 0; j < 25; j++) cp.out25[c][j] = p[j];
        perm64(kb, p); for (int j = 0; j < 25; j++) cp.in25 [c][j] = p[j];
        K = Kn;
        ka = split_child(K, 1, 3);
        kb = split_child(K, 2, 3);
        perm64(ka, p); for (int j = 0; j < 10; j++) cp.out10[c][j] = p[j];
        perm64(kb, p); for (int j = 0; j < 10; j++) cp.in10 [c][j] = p[j];
    }
}

} // namespace

// ---------------- device helpers ----------------
__device__ __forceinline__ ull ffma2(ull a, ull b, ull c) {
    ull d;
    asm("fma.rn.f32x2 %0, %1, %2, %3;" : "=l"(d) : "l"(a), "l"(b), "l"(c));
    return d;
}
__device__ __forceinline__ ull pack2(float x, float y) {
    ull r;
    asm("mov.b64 %0, {%1, %2};" : "=l"(r) : "f"(x), "f"(y));
    return r;
}
__device__ __forceinline__ float sigf(float x) { return 1.0f / (1.0f + expf(-x)); }

// ---------------- kernels (non-GEMM: identical to the 200.3us R5 version) ----------------

__global__ void k_sample(const int* __restrict__ nodes1, const int* __restrict__ nodes2,
                         const int* __restrict__ nout, const int* __restrict__ nin,
                         ColsParam cp) {
    int c = blockIdx.y, b = blockIdx.x, t = threadIdx.x; // t in [0,50)
    int v = (c ? nodes2 : nodes1)[b];
    int idx = (t < 25) ? nout[v * DEG + cp.out25[c][t]]
                       : nin [v * DEG + cp.in25 [c][t - 25]];
    g_s1[c][b * 50 + t] = idx;
}

__global__ __launch_bounds__(128) void k_agg_hop1(const int* __restrict__ nout,
                                                  const int* __restrict__ nin,
                                                  const float* __restrict__ feat,
                                                  ColsParam cp) {
    int c = blockIdx.y;
    int i = blockIdx.x;
    int f = threadIdx.x;
    __shared__ int nb[20];
    int s = g_s1[c][i];
    if (f < 10)       nb[f] = nout[s * DEG + cp.out10[c][f]];
    else if (f < 20)  nb[f] = nin [s * DEG + cp.in10 [c][f - 10]];
    __syncthreads();
    float self = feat[(size_t)s * FD + f];
    float so = 0.f, si = 0.f;
#pragma unroll
    for (int j = 0; j < 10; j++)  so += feat[(size_t)nb[j] * FD + f];
#pragma unroll
    for (int j = 10; j < 20; j++) si += feat[(size_t)nb[j] * FD + f];
    float* o = g_agg1 + ((size_t)c * S1N + i) * 384;
    o[f]        = self;
    o[128 + f]  = so / 10.0f;
    o[256 + f]  = si / 10.0f;
}

__global__ __launch_bounds__(128) void k_agg_hop0(const int* __restrict__ nodes1,
                                                  const int* __restrict__ nodes2,
                                                  const float* __restrict__ feat) {
    int c = blockIdx.y, b = blockIdx.x, f = threadIdx.x;
    int v = (c ? nodes2 : nodes1)[b];
    const int* s1 = &g_s1[c][b * 50];
    float self = feat[(size_t)v * FD + f];
    float so = 0.f, si = 0.f;
#pragma unroll 5
    for (int j = 0; j < 25; j++)  so += feat[(size_t)s1[j] * FD + f];
#pragma unroll 5
    for (int j = 25; j < 50; j++) si += feat[(size_t)s1[j] * FD + f];
    float* o = g_agg0 + (size_t)(c * BB + b) * 384;
    o[f]       = self;
    o[128 + f] = so / 25.0f;
    o[256 + f] = si / 25.0f;
}

// ---- BIG GEMM ----
// C[M1,128] = sigmoid(agg1[M1,384] @ W[384,128]) with packed f32x2 FFMA.
// Tile 64x128, BK=16, 256 threads. Thread (ty=tid>>5, tx=tid&31):
//   rows ty*8..ty*8+7, col pairs {tx, tx+32} (cols 2tx,2tx+1,2tx+64,2tx+65).
// A duplicated {a,a} in smem, read warp-uniform (LDS broadcast, conflict-free).
// B plain floats, LDS.64 at 8B*tx stride (even/odd bank pairs, conflict-free).
__global__ __launch_bounds__(256) void k_gemm_h1(const float* __restrict__ W) {
    __shared__ __align__(16) ull   sA2[16][66];   // [kk][row] = {a,a}
    __shared__ __align__(16) float sB [16][132];  // [kk][col]
    const float* A = g_agg1;
    const int bm  = blockIdx.x * 64;
    const int tid = threadIdx.x;
    const int tx  = tid & 31;
    const int ty  = tid >> 5;
    const int r   = tid >> 2, q   = tid & 3;   // A stage: row r, k-quad q
    const int kr  = tid >> 4, c16 = tid & 15;  // B stage: k-row kr, 8-col chunk c16

    ull acc[8][2];
#pragma unroll
    for (int i = 0; i < 8; i++) { acc[i][0] = 0ull; acc[i][1] = 0ull; }

    for (int k0 = 0; k0 < 384; k0 += 16) {
        float4 av = *(const float4*)&A[(size_t)(bm + r) * 384 + k0 + q * 4];
        sA2[q * 4 + 0][r] = pack2(av.x, av.x);
        sA2[q * 4 + 1][r] = pack2(av.y, av.y);
        sA2[q * 4 + 2][r] = pack2(av.z, av.z);
        sA2[q * 4 + 3][r] = pack2(av.w, av.w);
        *(float4*)&sB[kr][c16 * 8]     = *(const float4*)&W[(size_t)(k0 + kr) * 128 + c16 * 8];
        *(float4*)&sB[kr][c16 * 8 + 4] = *(const float4*)&W[(size_t)(k0 + kr) * 128 + c16 * 8 + 4];
        __syncthreads();
#pragma unroll
        for (int kk = 0; kk < 16; kk++) {
            ull a[8];
            *(ulonglong2*)&a[0] = *(const ulonglong2*)&sA2[kk][ty * 8 + 0];
            *(ulonglong2*)&a[2] = *(const ulonglong2*)&sA2[kk][ty * 8 + 2];
            *(ulonglong2*)&a[4] = *(const ulonglong2*)&sA2[kk][ty * 8 + 4];
            *(ulonglong2*)&a[6] = *(const ulonglong2*)&sA2[kk][ty * 8 + 6];
            ull b0 = *(const ull*)&sB[kk][2 * tx];
            ull b1 = *(const ull*)&sB[kk][2 * tx + 64];
#pragma unroll
            for (int i = 0; i < 8; i++) {
                acc[i][0] = ffma2(a[i], b0, acc[i][0]);
                acc[i][1] = ffma2(a[i], b1, acc[i][1]);
            }
        }
        __syncthreads();
    }
#pragma unroll
    for (int i = 0; i < 8; i++) {
        int row = bm + ty * 8 + i;
        union { ull u; float2 f; } p0, p1;
        p0.u = acc[i][0]; p1.u = acc[i][1];
        float2 o0 = make_float2(sigf(p0.f.x), sigf(p0.f.y));
        float2 o1 = make_float2(sigf(p1.f.x), sigf(p1.f.y));
        *(float2*)&g_h1[(size_t)row * 128 + 2 * tx]      = o0;
        *(float2*)&g_h1[(size_t)row * 128 + 2 * tx + 64] = o1;
    }
}

// small scalar SGEMM body for the tail GEMMs (unchanged from R5)
template <int BM, int TM>
__device__ __forceinline__ void sgemm_sig_body(const float* __restrict__ A,
                                               const float* __restrict__ W,
                                               float* __restrict__ C,
                                               int M, int bm) {
    __shared__ float sA[16][BM + 1];
    __shared__ float sB[16][128];
    int tid = threadIdx.x;
    int tx = tid & 31;
    int ty = tid >> 5;
    float4 acc[TM];
#pragma unroll
    for (int i = 0; i < TM; i++) acc[i] = make_float4(0.f, 0.f, 0.f, 0.f);

    for (int k0 = 0; k0 < 384; k0 += 16) {
        if (tid < BM * 4) {
            int r = tid >> 2, kq = tid & 3;
            float4 v = *(const float4*)&A[(size_t)(bm + r) * 384 + k0 + kq * 4];
            sA[kq * 4 + 0][r] = v.x; sA[kq * 4 + 1][r] = v.y;
            sA[kq * 4 + 2][r] = v.z; sA[kq * 4 + 3][r] = v.w;
        }
        {
            int l = tid, kr = l >> 5, c4 = l & 31;
            *(float4*)&sB[kr][c4 * 4] = *(const float4*)&W[(size_t)(k0 + kr) * 128 + c4 * 4];
            l += 256; kr = l >> 5; c4 = l & 31;
            *(float4*)&sB[kr][c4 * 4] = *(const float4*)&W[(size_t)(k0 + kr) * 128 + c4 * 4];
        }
        __syncthreads();
#pragma unroll
        for (int kk = 0; kk < 16; kk++) {
            float4 bv = *(const float4*)&sB[kk][tx * 4];
#pragma unroll
            for (int i = 0; i < TM; i++) {
                float a = sA[kk][ty * TM + i];
                acc[i].x += a * bv.x; acc[i].y += a * bv.y;
                acc[i].z += a * bv.z; acc[i].w += a * bv.w;
            }
        }
        __syncthreads();
    }
#pragma unroll
    for (int i = 0; i < TM; i++) {
        int r = bm + ty * TM + i;
        if (r < M) {
            float4 v = acc[i];
            v.x = sigf(v.x); v.y = sigf(v.y); v.z = sigf(v.z); v.w = sigf(v.w);
            *(float4*)&C[(size_t)r * 128 + tx * 4] = v;
        }
    }
}

__global__ __launch_bounds__(256) void k_gemm_h0(const float* __restrict__ W) {
    sgemm_sig_body<16, 2>(g_agg0, W, g_h0, 2 * BB, blockIdx.x * 16);
}
__global__ __launch_bounds__(256) void k_gemm_heads(const float* __restrict__ Wm,
                                                    const float* __restrict__ Ws,
                                                    const float* __restrict__ Wp) {
    const float* W = (blockIdx.z == 0) ? Wm : (blockIdx.z == 1) ? Ws : Wp;
    sgemm_sig_body<16, 2>(g_aggL1, W, g_head[blockIdx.z], 2 * BB, blockIdx.x * 16);
}

__global__ __launch_bounds__(128) void k_aggL1() {
    int c = blockIdx.y, b = blockIdx.x, f = threadIdx.x;
    const float* h1 = g_h1 + (size_t)(c * S1N + b * 50) * 128;
    float self = g_h0[(size_t)(c * BB + b) * 128 + f];
    float s0 = 0.f, s1v = 0.f;
#pragma unroll 5
    for (int j = 0; j < 25; j++)  s0  += h1[(size_t)j * 128 + f];
#pragma unroll 5
    for (int j = 25; j < 50; j++) s1v += h1[(size_t)j * 128 + f];
    float* o = g_aggL1 + (size_t)(c * BB + b) * 384;
    o[f]       = self;
    o[128 + f] = s0  / 25.0f;
    o[256 + f] = s1v / 25.0f;
}

__global__ __launch_bounds__(256) void k_final(const float* __restrict__ Wm,
                                               const float* __restrict__ Ws,
                                               const float* __restrict__ Wp,
                                               float* __restrict__ out) {
    __shared__ float sW[128 * 64];
    __shared__ float sH[16 * 128];
    int slot = blockIdx.x, rt = blockIdx.y, tid = threadIdx.x;
    int chain = slot / 3, head = slot % 3;
    const float* Wd = (head == 0) ? Wm : (head == 1) ? Ws : Wp;
    const float* H = &g_head[head][(size_t)(chain * BB + rt * 16) * 128];
    for (int l = tid; l < 128 * 64; l += 256) sW[l] = Wd[l];
    for (int l = tid; l < 16 * 128; l += 256) sH[l] = H[l];
    __syncthreads();
    int d = tid & 63, rg = tid >> 6;
#pragma unroll
    for (int ii = 0; ii < 4; ii++) {
        int r = rg * 4 + ii;
        float acc = 0.f;
#pragma unroll 8
        for (int k = 0; k < 128; k++) acc += sH[r * 128 + k] * sW[k * 64 + d];
        out[((size_t)slot * BB + rt * 16 + r) * 64 + d] = acc;
    }
}

// ---------------- launcher ----------------
extern "C" void kernel_launch(void* const* d_in, const int* in_sizes, int n_in,
                              void* d_out, int out_size) {
    (void)in_sizes; (void)n_in; (void)out_size;
    const int*   nodes1 = (const int*)  d_in[0];
    const int*   nodes2 = (const int*)  d_in[1];
    const int*   nout   = (const int*)  d_in[2];
    const int*   nin    = (const int*)  d_in[3];
    const float* feat   = (const float*)d_in[4];
    const float* W_in   = (const float*)d_in[5];
    const float* W_mean = (const float*)d_in[6];
    const float* W_std  = (const float*)d_in[7];
    const float* W_pi   = (const float*)d_in[8];
    const float* Wd_mean = (const float*)d_in[11];
    const float* Wd_std  = (const float*)d_in[12];
    const float* Wd_pi   = (const float*)d_in[13];
    float* out = (float*)d_out;

    ColsParam cp;
    compute_cols(cp);

    k_sample  <<<dim3(BB, 2),   50>>>(nodes1, nodes2, nout, nin, cp);
    k_agg_hop1<<<dim3(S1N, 2), 128>>>(nout, nin, feat, cp);
    k_agg_hop0<<<dim3(BB, 2),  128>>>(nodes1, nodes2, feat);
    k_gemm_h1 <<<M1 / 64, 256>>>(W_in);
    k_gemm_h0 <<<(2 * BB) / 16, 256>>>(W_in);
    k_aggL1   <<<dim3(BB, 2), 128>>>();
    k_gemm_heads<<<dim3((2 * BB) / 16, 1, 3), 256>>>(W_mean, W_std, W_pi);
    k_final   <<<dim3(6, BB / 16), 256>>>(Wd_mean, Wd_std, Wd_pi, out);
}